// round 1
// baseline (speedup 1.0000x reference)
#include <cuda_runtime.h>
#include <cuda_bf16.h>
#include <math_constants.h>

// ---------------------------------------------------------------------------
// Problem constants
// ---------------------------------------------------------------------------
#define BATCH   8
#define SEQ     1024
#define DIM     768
#define HEADS   12
#define HDIM    64
#define MROWS   (BATCH * SEQ)        // 8192
#define QKVCOLS (3 * DIM)            // 2304

// Scratch (device globals per allocation rules)
__device__ float g_qkv[MROWS * QKVCOLS];   // [8192, 2304] row-major
__device__ float g_attn[MROWS * DIM];      // [8192, 768]  row-major (B,N,C)

// ---------------------------------------------------------------------------
// GEMM with bias: C[M,N] = A[M,K] * B[K,N] + bias[N]
// 128x128 block tile, BK=8, 8x8 per-thread microtile, 256 threads.
// Requires M%128==0, N%128==0, K%8==0 (true for all our shapes).
// ---------------------------------------------------------------------------
#define BM 128
#define BN 128
#define BK 8
#define TM 8
#define TN 8

__global__ __launch_bounds__(256, 2)
void gemm_bias_kernel(const float* __restrict__ A,
                      const float* __restrict__ B,
                      const float* __restrict__ bias,
                      float* __restrict__ C,
                      int M, int N, int K) {
    __shared__ float As[BK * BM];   // transposed: As[k][m]
    __shared__ float Bs[BK * BN];   // Bs[k][n]

    const int tid = threadIdx.x;
    const int cRow = blockIdx.y;
    const int cCol = blockIdx.x;

    const int threadCol = tid % (BN / TN);   // 0..15
    const int threadRow = tid / (BN / TN);   // 0..15

    A += (size_t)cRow * BM * K;
    B += cCol * BN;
    C += (size_t)cRow * BM * N + cCol * BN;

    // A tile load: each thread loads one float4 along K (BK=8 -> 2 float4 per row)
    const int innerRowA = tid / (BK / 4);   // 0..127
    const int innerColA = tid % (BK / 4);   // 0..1
    // B tile load: each thread loads one float4 along N
    const int innerRowB = tid / (BN / 4);   // 0..7
    const int innerColB = tid % (BN / 4);   // 0..31

    float acc[TM][TN] = {};
    float regM[TM], regN[TN];

    for (int kb = 0; kb < K; kb += BK) {
        float4 a4 = *reinterpret_cast<const float4*>(A + innerRowA * K + innerColA * 4);
        As[(innerColA * 4 + 0) * BM + innerRowA] = a4.x;
        As[(innerColA * 4 + 1) * BM + innerRowA] = a4.y;
        As[(innerColA * 4 + 2) * BM + innerRowA] = a4.z;
        As[(innerColA * 4 + 3) * BM + innerRowA] = a4.w;
        *reinterpret_cast<float4*>(Bs + innerRowB * BN + innerColB * 4) =
            *reinterpret_cast<const float4*>(B + innerRowB * N + innerColB * 4);
        __syncthreads();

        A += BK;
        B += (size_t)BK * N;

        #pragma unroll
        for (int k = 0; k < BK; ++k) {
            *reinterpret_cast<float4*>(&regM[0]) =
                *reinterpret_cast<float4*>(&As[k * BM + threadRow * TM]);
            *reinterpret_cast<float4*>(&regM[4]) =
                *reinterpret_cast<float4*>(&As[k * BM + threadRow * TM + 4]);
            *reinterpret_cast<float4*>(&regN[0]) =
                *reinterpret_cast<float4*>(&Bs[k * BN + threadCol * TN]);
            *reinterpret_cast<float4*>(&regN[4]) =
                *reinterpret_cast<float4*>(&Bs[k * BN + threadCol * TN + 4]);
            #pragma unroll
            for (int i = 0; i < TM; ++i)
                #pragma unroll
                for (int j = 0; j < TN; ++j)
                    acc[i][j] = fmaf(regM[i], regN[j], acc[i][j]);
        }
        __syncthreads();
    }

    const float* brow = bias + cCol * BN + threadCol * TN;
    float4 b0 = *reinterpret_cast<const float4*>(brow);
    float4 b1 = *reinterpret_cast<const float4*>(brow + 4);
    #pragma unroll
    for (int i = 0; i < TM; ++i) {
        float* crow = C + (size_t)(threadRow * TM + i) * N + threadCol * TN;
        float4 o0 = make_float4(acc[i][0] + b0.x, acc[i][1] + b0.y,
                                acc[i][2] + b0.z, acc[i][3] + b0.w);
        float4 o1 = make_float4(acc[i][4] + b1.x, acc[i][5] + b1.y,
                                acc[i][6] + b1.z, acc[i][7] + b1.w);
        *reinterpret_cast<float4*>(crow)     = o0;
        *reinterpret_cast<float4*>(crow + 4) = o1;
    }
}

// ---------------------------------------------------------------------------
// Flash attention: one block per (b, h, 64-query tile).
// Streams 16 KV tiles of 64 keys; online softmax; never materializes attn.
// Q and K stored d-major (transposed) in smem so fragment loads are float4.
// Threads: 256 as (tx=16, ty=16); each thread owns a 4x4 tile of S and of O.
// ---------------------------------------------------------------------------
#define ATT_LDA 68                       // padded stride (mult of 4, !mult of 32)
#define ATT_SMEM_BYTES (4 * 64 * ATT_LDA * 4)

__global__ __launch_bounds__(256)
void attn_kernel(const float* __restrict__ qkv, float* __restrict__ out) {
    extern __shared__ float sm[];
    float* Qt = sm;                       // [64][ATT_LDA], d-major: Qt[d][r]
    float* Kt = Qt + 64 * ATT_LDA;        // [64][ATT_LDA], d-major: Kt[d][c]
    float* Vs = Kt + 64 * ATT_LDA;        // [64][ATT_LDA], row-major: Vs[c][d]
    float* Ps = Vs + 64 * ATT_LDA;        // [64][ATT_LDA], row-major: Ps[r][c]

    const int qt = blockIdx.x;            // query tile 0..15
    const int h  = blockIdx.y;            // head 0..11
    const int b  = blockIdx.z;            // batch 0..7

    const int tid = threadIdx.x;
    const int tx = tid % 16;
    const int ty = tid / 16;

    const float scale = 0.125f;           // 1/sqrt(64)

    const int loadRow = tid / 16;         // 0..15 (16 rows per pass)
    const int loadD   = (tid % 16) * 4;   // float4 along d

    // Load Q tile transposed, pre-scaled
    {
        const float* qbase = qkv + ((size_t)(b * SEQ + qt * 64)) * QKVCOLS + h * HDIM;
        #pragma unroll
        for (int rr = loadRow; rr < 64; rr += 16) {
            float4 q4 = *reinterpret_cast<const float4*>(qbase + (size_t)rr * QKVCOLS + loadD);
            Qt[(loadD + 0) * ATT_LDA + rr] = q4.x * scale;
            Qt[(loadD + 1) * ATT_LDA + rr] = q4.y * scale;
            Qt[(loadD + 2) * ATT_LDA + rr] = q4.z * scale;
            Qt[(loadD + 3) * ATT_LDA + rr] = q4.w * scale;
        }
    }

    float m_i[4], l_i[4], o[4][4];
    #pragma unroll
    for (int i = 0; i < 4; ++i) {
        m_i[i] = -CUDART_INF_F;
        l_i[i] = 0.0f;
        #pragma unroll
        for (int j = 0; j < 4; ++j) o[i][j] = 0.0f;
    }

    for (int t = 0; t < SEQ / 64; ++t) {
        __syncthreads();   // previous P@V done (and Q load visible on t==0 via next sync)

        // Load K tile (transposed) and V tile
        const float* kbase = qkv + ((size_t)(b * SEQ + t * 64)) * QKVCOLS + DIM + h * HDIM;
        const float* vbase = kbase + DIM;   // +2*DIM total offset for V
        #pragma unroll
        for (int rr = loadRow; rr < 64; rr += 16) {
            float4 k4 = *reinterpret_cast<const float4*>(kbase + (size_t)rr * QKVCOLS + loadD);
            Kt[(loadD + 0) * ATT_LDA + rr] = k4.x;
            Kt[(loadD + 1) * ATT_LDA + rr] = k4.y;
            Kt[(loadD + 2) * ATT_LDA + rr] = k4.z;
            Kt[(loadD + 3) * ATT_LDA + rr] = k4.w;
            *reinterpret_cast<float4*>(&Vs[rr * ATT_LDA + loadD]) =
                *reinterpret_cast<const float4*>(vbase + (size_t)rr * QKVCOLS + loadD);
        }
        __syncthreads();

        // S = (Q*scale) @ K^T   (4x4 per thread)
        float s[4][4] = {};
        #pragma unroll 4
        for (int d = 0; d < 64; ++d) {
            float4 qv = *reinterpret_cast<float4*>(&Qt[d * ATT_LDA + ty * 4]);
            float4 kv = *reinterpret_cast<float4*>(&Kt[d * ATT_LDA + tx * 4]);
            float qa[4] = {qv.x, qv.y, qv.z, qv.w};
            float ka[4] = {kv.x, kv.y, kv.z, kv.w};
            #pragma unroll
            for (int i = 0; i < 4; ++i)
                #pragma unroll
                for (int j = 0; j < 4; ++j)
                    s[i][j] = fmaf(qa[i], ka[j], s[i][j]);
        }

        // Online softmax per row (row spread across the 16 tx lanes)
        #pragma unroll
        for (int i = 0; i < 4; ++i) {
            float rmax = fmaxf(fmaxf(s[i][0], s[i][1]), fmaxf(s[i][2], s[i][3]));
            #pragma unroll
            for (int off = 1; off < 16; off <<= 1)
                rmax = fmaxf(rmax, __shfl_xor_sync(0xffffffffu, rmax, off));
            float mnew = fmaxf(m_i[i], rmax);
            float alpha = __expf(m_i[i] - mnew);
            float rsum = 0.0f;
            #pragma unroll
            for (int j = 0; j < 4; ++j) {
                float p = __expf(s[i][j] - mnew);
                s[i][j] = p;
                rsum += p;
            }
            #pragma unroll
            for (int off = 1; off < 16; off <<= 1)
                rsum += __shfl_xor_sync(0xffffffffu, rsum, off);
            l_i[i] = l_i[i] * alpha + rsum;
            m_i[i] = mnew;
            #pragma unroll
            for (int j = 0; j < 4; ++j) o[i][j] *= alpha;
            // stage P
            #pragma unroll
            for (int j = 0; j < 4; ++j)
                Ps[(ty * 4 + i) * ATT_LDA + tx * 4 + j] = s[i][j];
        }
        __syncthreads();

        // O += P @ V
        #pragma unroll 4
        for (int c = 0; c < 64; ++c) {
            float4 vv = *reinterpret_cast<float4*>(&Vs[c * ATT_LDA + tx * 4]);
            float va[4] = {vv.x, vv.y, vv.z, vv.w};
            float p0 = Ps[(ty * 4 + 0) * ATT_LDA + c];
            float p1 = Ps[(ty * 4 + 1) * ATT_LDA + c];
            float p2 = Ps[(ty * 4 + 2) * ATT_LDA + c];
            float p3 = Ps[(ty * 4 + 3) * ATT_LDA + c];
            #pragma unroll
            for (int j = 0; j < 4; ++j) {
                o[0][j] = fmaf(p0, va[j], o[0][j]);
                o[1][j] = fmaf(p1, va[j], o[1][j]);
                o[2][j] = fmaf(p2, va[j], o[2][j]);
                o[3][j] = fmaf(p3, va[j], o[3][j]);
            }
        }
    }

    // Normalize and write out in [B, N, C] layout (C = h*64 + d)
    #pragma unroll
    for (int i = 0; i < 4; ++i) {
        float inv = 1.0f / l_i[i];
        size_t row = (size_t)(b * SEQ + qt * 64 + ty * 4 + i);
        float* orow = out + row * DIM + h * HDIM + tx * 4;
        float4 ov = make_float4(o[i][0] * inv, o[i][1] * inv, o[i][2] * inv, o[i][3] * inv);
        *reinterpret_cast<float4*>(orow) = ov;
    }
}

// ---------------------------------------------------------------------------
// Launch
// ---------------------------------------------------------------------------
extern "C" void kernel_launch(void* const* d_in, const int* in_sizes, int n_in,
                              void* d_out, int out_size) {
    const float* x      = (const float*)d_in[0];
    const float* w_qkv  = (const float*)d_in[1];
    const float* b_qkv  = (const float*)d_in[2];
    const float* w_proj = (const float*)d_in[3];
    const float* b_proj = (const float*)d_in[4];
    float* out = (float*)d_out;

    float* qkv;
    float* attn;
    cudaGetSymbolAddress((void**)&qkv,  g_qkv);
    cudaGetSymbolAddress((void**)&attn, g_attn);

    cudaFuncSetAttribute(attn_kernel,
                         cudaFuncAttributeMaxDynamicSharedMemorySize,
                         ATT_SMEM_BYTES);

    // 1) QKV projection: [8192,768] x [768,2304] + bias
    {
        dim3 grid(QKVCOLS / BN, MROWS / BM);
        gemm_bias_kernel<<<grid, 256>>>(x, w_qkv, b_qkv, qkv, MROWS, QKVCOLS, DIM);
    }
    // 2) Flash attention
    {
        dim3 grid(SEQ / 64, HEADS, BATCH);
        attn_kernel<<<grid, 256, ATT_SMEM_BYTES>>>(qkv, attn);
    }
    // 3) Output projection: [8192,768] x [768,768] + bias
    {
        dim3 grid(DIM / BN, MROWS / BM);
        gemm_bias_kernel<<<grid, 256>>>(attn, w_proj, b_proj, out, MROWS, DIM, DIM);
    }
}

// round 2
// speedup vs baseline: 2.7504x; 2.7504x over previous
#include <cuda_runtime.h>
#include <cuda_bf16.h>
#include <math_constants.h>
#include <cstdint>

// ---------------------------------------------------------------------------
// Problem constants
// ---------------------------------------------------------------------------
#define BATCH   8
#define SEQ     1024
#define DIM     768
#define HEADS   12
#define HDIM    64
#define MROWS   (BATCH * SEQ)        // 8192
#define QKVCOLS (3 * DIM)            // 2304

// Scratch (device globals per allocation rules)
__device__ float g_qkv[MROWS * QKVCOLS];   // [8192, 2304] row-major
__device__ float g_attn[MROWS * DIM];      // [8192, 768]  row-major

// ---------------------------------------------------------------------------
// tf32 helpers
// ---------------------------------------------------------------------------
__device__ __forceinline__ uint32_t f2tf32(float x) {
    uint32_t r;
    asm("cvt.rna.tf32.f32 %0, %1;" : "=r"(r) : "f"(x));
    return r;
}

__device__ __forceinline__ void mma_tf32(float c[4],
                                         uint32_t a0, uint32_t a1, uint32_t a2, uint32_t a3,
                                         uint32_t b0, uint32_t b1) {
    asm volatile(
        "mma.sync.aligned.m16n8k8.row.col.f32.tf32.tf32.f32 "
        "{%0,%1,%2,%3}, {%4,%5,%6,%7}, {%8,%9}, {%0,%1,%2,%3};\n"
        : "+f"(c[0]), "+f"(c[1]), "+f"(c[2]), "+f"(c[3])
        : "r"(a0), "r"(a1), "r"(a2), "r"(a3), "r"(b0), "r"(b1));
}

// ---------------------------------------------------------------------------
// TF32 tensor-core GEMM + bias: C[M,N] = A[M,K]*B[K,N] + bias[N]
// Block 128x128, BK=16, 256 threads = 8 warps (2x4), warp tile 64x32.
// Fragments loaded from padded smem (stride 136 -> conflict-free: banks 8*t4+g).
// ---------------------------------------------------------------------------
#define GBM 128
#define GBN 128
#define GBK 16
#define GLDS 136   // padded smem row stride (floats); 136 % 32 == 8

__global__ __launch_bounds__(256)
void gemm_tf32_kernel(const float* __restrict__ A,
                      const float* __restrict__ B,
                      const float* __restrict__ bias,
                      float* __restrict__ C,
                      int M, int N, int K) {
    __shared__ uint32_t As[GBK * GLDS];   // As[k][m] (transposed)
    __shared__ uint32_t Bs[GBK * GLDS];   // Bs[k][n]

    const int tid  = threadIdx.x;
    const int lane = tid & 31;
    const int wid  = tid >> 5;           // 0..7
    const int wr   = wid >> 2;           // 0..1  -> warp row base 64*wr
    const int wc   = wid & 3;            // 0..3  -> warp col base 32*wc
    const int g    = lane >> 2;          // 0..7
    const int t4   = lane & 3;           // 0..3

    const int bRow = blockIdx.y * GBM;
    const int bCol = blockIdx.x * GBN;

    // A loads: 128 rows x 16 cols; 4 threads/row (4 float4), 64 rows/pass, 2 passes
    const int arow = tid >> 2;           // 0..63
    const int acol = (tid & 3) * 4;      // 0,4,8,12
    // B loads: 16 rows x 128 cols; 32 threads/row, 8 rows/pass, 2 passes
    const int brow = tid >> 5;           // 0..7
    const int bcol = (tid & 31) * 4;

    float acc[4][4][4];
    #pragma unroll
    for (int i = 0; i < 4; ++i)
        #pragma unroll
        for (int j = 0; j < 4; ++j)
            #pragma unroll
            for (int r = 0; r < 4; ++r) acc[i][j][r] = 0.0f;

    const int wmb = wr * 64;   // warp m base within block
    const int wnb = wc * 32;   // warp n base within block

    for (int kb = 0; kb < K; kb += GBK) {
        // load A tile -> As[k][m] (tf32)
        #pragma unroll
        for (int p = 0; p < 2; ++p) {
            int r = arow + p * 64;
            float4 a4 = *reinterpret_cast<const float4*>(A + (size_t)(bRow + r) * K + kb + acol);
            As[(acol + 0) * GLDS + r] = f2tf32(a4.x);
            As[(acol + 1) * GLDS + r] = f2tf32(a4.y);
            As[(acol + 2) * GLDS + r] = f2tf32(a4.z);
            As[(acol + 3) * GLDS + r] = f2tf32(a4.w);
        }
        // load B tile -> Bs[k][n]
        #pragma unroll
        for (int p = 0; p < 2; ++p) {
            int r = brow + p * 8;
            float4 b4 = *reinterpret_cast<const float4*>(B + (size_t)(kb + r) * N + bCol + bcol);
            uint32_t* dst = &Bs[r * GLDS + bcol];
            dst[0] = f2tf32(b4.x);
            dst[1] = f2tf32(b4.y);
            dst[2] = f2tf32(b4.z);
            dst[3] = f2tf32(b4.w);
        }
        __syncthreads();

        #pragma unroll
        for (int ks = 0; ks < 2; ++ks) {
            const int k0 = ks * 8;
            uint32_t af[4][4];
            #pragma unroll
            for (int mt = 0; mt < 4; ++mt) {
                int base = (k0 + t4) * GLDS + wmb + mt * 16 + g;
                af[mt][0] = As[base];
                af[mt][1] = As[base + 8];
                af[mt][2] = As[base + 4 * GLDS];
                af[mt][3] = As[base + 4 * GLDS + 8];
            }
            uint32_t bf[4][2];
            #pragma unroll
            for (int nt = 0; nt < 4; ++nt) {
                int base = (k0 + t4) * GLDS + wnb + nt * 8 + g;
                bf[nt][0] = Bs[base];
                bf[nt][1] = Bs[base + 4 * GLDS];
            }
            #pragma unroll
            for (int mt = 0; mt < 4; ++mt)
                #pragma unroll
                for (int nt = 0; nt < 4; ++nt)
                    mma_tf32(acc[mt][nt], af[mt][0], af[mt][1], af[mt][2], af[mt][3],
                             bf[nt][0], bf[nt][1]);
        }
        __syncthreads();
    }

    // epilogue: bias + store (float2 per fragment row-half)
    #pragma unroll
    for (int nt = 0; nt < 4; ++nt) {
        int c = bCol + wnb + nt * 8 + 2 * t4;
        float bx = bias[c], by = bias[c + 1];
        #pragma unroll
        for (int mt = 0; mt < 4; ++mt) {
            int r0 = bRow + wmb + mt * 16 + g;
            float2 v0 = make_float2(acc[mt][nt][0] + bx, acc[mt][nt][1] + by);
            float2 v1 = make_float2(acc[mt][nt][2] + bx, acc[mt][nt][3] + by);
            *reinterpret_cast<float2*>(C + (size_t)r0 * N + c)       = v0;
            *reinterpret_cast<float2*>(C + (size_t)(r0 + 8) * N + c) = v1;
        }
    }
}

// ---------------------------------------------------------------------------
// Flash attention with tf32 tensor cores.
// One block per (b, h, 64-query tile); 128 threads = 4 warps; warp owns 16 queries.
// S = Q@K^T and O += P@V via mma.m16n8k8 (P round-trips through smem).
// ---------------------------------------------------------------------------
#define QK_LD 68   // stride for Qs/Ks/Ps (68 % 32 == 4 -> banks 4g+t4 distinct)
#define V_LD  72   // stride for Vs       (72 % 32 == 8 -> banks 8t4+g distinct)
#define ATT_SMEM_BYTES ((3 * 64 * QK_LD + 64 * V_LD) * 4)

__global__ __launch_bounds__(128)
void attn_tf32_kernel(const float* __restrict__ qkv, float* __restrict__ out) {
    extern __shared__ uint32_t sm[];
    uint32_t* Qs = sm;                    // [64][QK_LD]  (q, d)  pre-scaled tf32
    uint32_t* Ks = Qs + 64 * QK_LD;       // [64][QK_LD]  (key, d)
    uint32_t* Ps = Ks + 64 * QK_LD;       // [64][QK_LD]  (q, key) tf32
    uint32_t* Vs = Ps + 64 * QK_LD;       // [64][V_LD]   (key, d)

    const int qt = blockIdx.x;
    const int h  = blockIdx.y;
    const int b  = blockIdx.z;

    const int tid  = threadIdx.x;
    const int lane = tid & 31;
    const int wid  = tid >> 5;           // 0..3
    const int g    = lane >> 2;
    const int t4   = lane & 3;
    const int qw   = wid * 16;           // warp's query base within tile

    const float scale = 0.125f;          // 1/sqrt(64)

    const int lrow = tid >> 4;           // 0..7 (8 rows per pass)
    const int lcol = (tid & 15) * 4;     // float4 along d

    // Load Q tile (pre-scaled, tf32)
    {
        const float* qbase = qkv + ((size_t)(b * SEQ + qt * 64)) * QKVCOLS + h * HDIM;
        #pragma unroll
        for (int rr = lrow; rr < 64; rr += 8) {
            float4 q4 = *reinterpret_cast<const float4*>(qbase + (size_t)rr * QKVCOLS + lcol);
            Qs[rr * QK_LD + lcol + 0] = f2tf32(q4.x * scale);
            Qs[rr * QK_LD + lcol + 1] = f2tf32(q4.y * scale);
            Qs[rr * QK_LD + lcol + 2] = f2tf32(q4.z * scale);
            Qs[rr * QK_LD + lcol + 3] = f2tf32(q4.w * scale);
        }
    }

    float m_i[2] = {-CUDART_INF_F, -CUDART_INF_F};
    float l_i[2] = {0.0f, 0.0f};
    float oacc[8][4];
    #pragma unroll
    for (int nt = 0; nt < 8; ++nt)
        #pragma unroll
        for (int r = 0; r < 4; ++r) oacc[nt][r] = 0.0f;

    for (int t = 0; t < SEQ / 64; ++t) {
        __syncthreads();   // prior tile's PV done (covers Q store visibility at t=0)

        const float* kbase = qkv + ((size_t)(b * SEQ + t * 64)) * QKVCOLS + DIM + h * HDIM;
        const float* vbase = kbase + DIM;
        #pragma unroll
        for (int rr = lrow; rr < 64; rr += 8) {
            float4 k4 = *reinterpret_cast<const float4*>(kbase + (size_t)rr * QKVCOLS + lcol);
            Ks[rr * QK_LD + lcol + 0] = f2tf32(k4.x);
            Ks[rr * QK_LD + lcol + 1] = f2tf32(k4.y);
            Ks[rr * QK_LD + lcol + 2] = f2tf32(k4.z);
            Ks[rr * QK_LD + lcol + 3] = f2tf32(k4.w);
            float4 v4 = *reinterpret_cast<const float4*>(vbase + (size_t)rr * QKVCOLS + lcol);
            Vs[rr * V_LD + lcol + 0] = f2tf32(v4.x);
            Vs[rr * V_LD + lcol + 1] = f2tf32(v4.y);
            Vs[rr * V_LD + lcol + 2] = f2tf32(v4.z);
            Vs[rr * V_LD + lcol + 3] = f2tf32(v4.w);
        }
        __syncthreads();

        // --- S = Q @ K^T  (warp: 16 queries x 64 keys) ---
        float sacc[8][4];
        #pragma unroll
        for (int nt = 0; nt < 8; ++nt)
            #pragma unroll
            for (int r = 0; r < 4; ++r) sacc[nt][r] = 0.0f;

        #pragma unroll
        for (int ks = 0; ks < 8; ++ks) {
            int ab = (qw + g) * QK_LD + ks * 8 + t4;
            uint32_t a0 = Qs[ab];
            uint32_t a1 = Qs[ab + 8 * QK_LD];
            uint32_t a2 = Qs[ab + 4];
            uint32_t a3 = Qs[ab + 8 * QK_LD + 4];
            #pragma unroll
            for (int nt = 0; nt < 8; ++nt) {
                int bb = (nt * 8 + g) * QK_LD + ks * 8 + t4;
                mma_tf32(sacc[nt], a0, a1, a2, a3, Ks[bb], Ks[bb + 4]);
            }
        }

        // --- online softmax (two row-halves: g and g+8) ---
        #pragma unroll
        for (int rh = 0; rh < 2; ++rh) {
            float mx = -CUDART_INF_F;
            #pragma unroll
            for (int nt = 0; nt < 8; ++nt)
                mx = fmaxf(mx, fmaxf(sacc[nt][rh * 2], sacc[nt][rh * 2 + 1]));
            mx = fmaxf(mx, __shfl_xor_sync(0xffffffffu, mx, 1));
            mx = fmaxf(mx, __shfl_xor_sync(0xffffffffu, mx, 2));
            float mnew  = fmaxf(m_i[rh], mx);
            float alpha = __expf(m_i[rh] - mnew);
            float rsum = 0.0f;
            int prow = (qw + g + rh * 8) * QK_LD;
            #pragma unroll
            for (int nt = 0; nt < 8; ++nt) {
                float p0 = __expf(sacc[nt][rh * 2]     - mnew);
                float p1 = __expf(sacc[nt][rh * 2 + 1] - mnew);
                rsum += p0 + p1;
                Ps[prow + nt * 8 + 2 * t4]     = f2tf32(p0);
                Ps[prow + nt * 8 + 2 * t4 + 1] = f2tf32(p1);
            }
            rsum += __shfl_xor_sync(0xffffffffu, rsum, 1);
            rsum += __shfl_xor_sync(0xffffffffu, rsum, 2);
            l_i[rh] = l_i[rh] * alpha + rsum;
            m_i[rh] = mnew;
            #pragma unroll
            for (int nt = 0; nt < 8; ++nt) {
                oacc[nt][rh * 2]     *= alpha;
                oacc[nt][rh * 2 + 1] *= alpha;
            }
        }
        __syncwarp();   // Ps rows are warp-private; order writes before reads

        // --- O += P @ V  (k = 64 keys, n = 64 d) ---
        #pragma unroll
        for (int ks = 0; ks < 8; ++ks) {
            int ab = (qw + g) * QK_LD + ks * 8 + t4;
            uint32_t a0 = Ps[ab];
            uint32_t a1 = Ps[ab + 8 * QK_LD];
            uint32_t a2 = Ps[ab + 4];
            uint32_t a3 = Ps[ab + 8 * QK_LD + 4];
            #pragma unroll
            for (int nt = 0; nt < 8; ++nt) {
                int bb = (ks * 8 + t4) * V_LD + nt * 8 + g;
                mma_tf32(oacc[nt], a0, a1, a2, a3, Vs[bb], Vs[bb + 4 * V_LD]);
            }
        }
    }

    // normalize + write [B, N, C] (C = h*64 + d)
    #pragma unroll
    for (int rh = 0; rh < 2; ++rh) {
        float inv = 1.0f / l_i[rh];
        size_t row = (size_t)(b * SEQ + qt * 64 + qw + g + rh * 8);
        #pragma unroll
        for (int nt = 0; nt < 8; ++nt) {
            float2 v = make_float2(oacc[nt][rh * 2] * inv, oacc[nt][rh * 2 + 1] * inv);
            *reinterpret_cast<float2*>(out + row * DIM + h * HDIM + nt * 8 + 2 * t4) = v;
        }
    }
}

// ---------------------------------------------------------------------------
// Launch
// ---------------------------------------------------------------------------
extern "C" void kernel_launch(void* const* d_in, const int* in_sizes, int n_in,
                              void* d_out, int out_size) {
    const float* x      = (const float*)d_in[0];
    const float* w_qkv  = (const float*)d_in[1];
    const float* b_qkv  = (const float*)d_in[2];
    const float* w_proj = (const float*)d_in[3];
    const float* b_proj = (const float*)d_in[4];
    float* out = (float*)d_out;

    float* qkv;
    float* attn;
    cudaGetSymbolAddress((void**)&qkv,  g_qkv);
    cudaGetSymbolAddress((void**)&attn, g_attn);

    cudaFuncSetAttribute(attn_tf32_kernel,
                         cudaFuncAttributeMaxDynamicSharedMemorySize,
                         ATT_SMEM_BYTES);

    // 1) QKV projection
    {
        dim3 grid(QKVCOLS / GBN, MROWS / GBM);
        gemm_tf32_kernel<<<grid, 256>>>(x, w_qkv, b_qkv, qkv, MROWS, QKVCOLS, DIM);
    }
    // 2) Flash attention
    {
        dim3 grid(SEQ / 64, HEADS, BATCH);
        attn_tf32_kernel<<<grid, 128, ATT_SMEM_BYTES>>>(qkv, attn);
    }
    // 3) Output projection
    {
        dim3 grid(DIM / GBN, MROWS / GBM);
        gemm_tf32_kernel<<<grid, 256>>>(attn, w_proj, b_proj, out, MROWS, DIM, DIM);
    }
}